// round 1
// baseline (speedup 1.0000x reference)
#include <cuda_runtime.h>
#include <math.h>

// Problem constants
#define NTOK 16384
#define DIM  2048
#define NEXP 64
#define NK   (NTOK * 2)          // 32768 (token, slot) pairs

// GEMM tiling
#define BM 64                    // tokens per CTA
#define BK 32                    // k-chunk
#define THREADS 128
#define NBLK (NTOK / BM)         // 256 CTAs; each also owns 128 flat slots

// Output layout: concatenation of reference return values (all as fp32)
#define OFF_TOK   0
#define OFF_REV   NK
#define OFF_CW    (2 * NK)
#define OFF_SPL   (3 * NK)
#define OFF_PROBS (3 * NK + NEXP)

// Scratch (no allocations allowed -> __device__ globals)
__device__ int g_flat_idx[NK];
__device__ int g_blockHist[NBLK * NEXP];
__device__ int g_blockBase[NBLK * NEXP];

// ---------------------------------------------------------------------------
// Kernel 1: fused GEMM (logits) + softmax + top-2 + combine weights + probs
//           + per-block expert histogram.
// Grid: NBLK x THREADS.  CTA computes logits[64 tokens][64 experts].
// ---------------------------------------------------------------------------
__global__ __launch_bounds__(THREADS) void gate_fused_kernel(
    const float* __restrict__ A,   // [NTOK, DIM]
    const float* __restrict__ W,   // [NEXP, DIM]
    float* __restrict__ out)
{
    __shared__ float As[BK][BM + 1];     // +1 pad: conflict-free transpose store
    __shared__ float Ws[BK][NEXP + 1];
    __shared__ float Cs[BM][NEXP + 1];
    __shared__ int   hist[NEXP];

    const int tid  = threadIdx.x;
    const int blk  = blockIdx.x;
    const int tok0 = blk * BM;

    const int tx = tid & 15;    // expert group: experts tx*4 .. tx*4+3
    const int ty = tid >> 4;    // token group:  tokens  ty*8 .. ty*8+7
    const int lr = tid >> 3;    // loader row   0..15
    const int lc = tid & 7;     // loader col4  0..7

    float acc[8][4];
#pragma unroll
    for (int i = 0; i < 8; i++)
#pragma unroll
        for (int j = 0; j < 4; j++) acc[i][j] = 0.f;

    const float* Ablk = A + (size_t)tok0 * DIM;

    for (int k0 = 0; k0 < DIM; k0 += BK) {
        // Load A chunk [64 x 32] transposed into As[k][t]
#pragma unroll
        for (int p = 0; p < 4; ++p) {
            int r = lr + p * 16;
            float4 v = *reinterpret_cast<const float4*>(Ablk + (size_t)r * DIM + k0 + lc * 4);
            As[lc * 4 + 0][r] = v.x; As[lc * 4 + 1][r] = v.y;
            As[lc * 4 + 2][r] = v.z; As[lc * 4 + 3][r] = v.w;
        }
        // Load W chunk [64 x 32] transposed into Ws[k][e]
#pragma unroll
        for (int p = 0; p < 4; ++p) {
            int r = lr + p * 16;
            float4 v = *reinterpret_cast<const float4*>(W + (size_t)r * DIM + k0 + lc * 4);
            Ws[lc * 4 + 0][r] = v.x; Ws[lc * 4 + 1][r] = v.y;
            Ws[lc * 4 + 2][r] = v.z; Ws[lc * 4 + 3][r] = v.w;
        }
        __syncthreads();

#pragma unroll 8
        for (int k = 0; k < BK; ++k) {
            float a[8], w[4];
#pragma unroll
            for (int i = 0; i < 8; i++) a[i] = As[k][ty * 8 + i];
#pragma unroll
            for (int j = 0; j < 4; j++) w[j] = Ws[k][tx * 4 + j];
#pragma unroll
            for (int i = 0; i < 8; i++)
#pragma unroll
                for (int j = 0; j < 4; j++)
                    acc[i][j] = fmaf(a[i], w[j], acc[i][j]);
        }
        __syncthreads();
    }

    // Stage logits to smem
#pragma unroll
    for (int i = 0; i < 8; i++)
#pragma unroll
        for (int j = 0; j < 4; j++)
            Cs[ty * 8 + i][tx * 4 + j] = acc[i][j];
    if (tid < NEXP) hist[tid] = 0;
    __syncthreads();

    // One thread per token: softmax + top-2 + combine weights
    if (tid < BM) {
        const int t = tid;
        float mx = -1e30f;
#pragma unroll 8
        for (int e = 0; e < NEXP; e++) mx = fmaxf(mx, Cs[t][e]);
        float s = 0.f;
#pragma unroll 8
        for (int e = 0; e < NEXP; e++) {
            float ex = expf(Cs[t][e] - mx);
            Cs[t][e] = ex;
            s += ex;
        }
        float inv = 1.0f / s;
        float v1 = -1.f, v2 = -1.f;
        int   i1 = 0, i2 = 0;
#pragma unroll 8
        for (int e = 0; e < NEXP; e++) {
            float p = Cs[t][e] * inv;
            Cs[t][e] = p;                       // probs in place
            if (p > v1)      { v2 = v1; i2 = i1; v1 = p; i1 = e; }
            else if (p > v2) { v2 = p; i2 = e; }
        }
        // combine = softmax([v1, v2]) over the prob VALUES (reference quirk)
        float eb   = expf(v2 - v1);             // v1 >= v2
        float invd = 1.0f / (1.0f + eb);
        int flat = (tok0 + t) * 2;
        out[OFF_CW + flat]     = invd;
        out[OFF_CW + flat + 1] = eb * invd;
        g_flat_idx[flat]     = i1;
        g_flat_idx[flat + 1] = i2;
        atomicAdd(&hist[i1], 1);
        atomicAdd(&hist[i2], 1);
    }
    __syncthreads();

    if (tid < NEXP) g_blockHist[blk * NEXP + tid] = hist[tid];

    // Coalesced probs writeback
    float* pout = out + OFF_PROBS + (size_t)tok0 * NEXP;
    for (int idx = tid; idx < BM * NEXP; idx += THREADS) {
        int t = idx >> 6, e = idx & 63;
        pout[idx] = Cs[t][e];
    }
}

// ---------------------------------------------------------------------------
// Kernel 2 (1 CTA, 64 threads): per-expert scan across blocks + expert offsets.
// Writes input_splits, and the stable base offset for each (block, expert).
// ---------------------------------------------------------------------------
__global__ void gate_scan_kernel(float* __restrict__ out)
{
    __shared__ int totals[NEXP];
    __shared__ int offs[NEXP];
    const int e = threadIdx.x;          // 64 threads, one expert each

    int run = 0;
#pragma unroll 8
    for (int b = 0; b < NBLK; b++) run += g_blockHist[b * NEXP + e];
    totals[e] = run;
    __syncthreads();

    if (e == 0) {
        int s = 0;
        for (int i = 0; i < NEXP; i++) { offs[i] = s; s += totals[i]; }
    }
    __syncthreads();

    out[OFF_SPL + e] = (float)totals[e];

    int base = offs[e];
#pragma unroll 8
    for (int b = 0; b < NBLK; b++) {
        g_blockBase[b * NEXP + e] = base;
        base += g_blockHist[b * NEXP + e];
    }
}

// ---------------------------------------------------------------------------
// Kernel 3 (NBLK x 128): stable intra-block rank (match_any + warp histogram
// prefix) -> final sorted position; scatter token_order / reversed_ordering.
// ---------------------------------------------------------------------------
__global__ __launch_bounds__(128) void gate_scatter_kernel(float* __restrict__ out)
{
    __shared__ int warpHist[4][NEXP];
    __shared__ int base_s[NEXP];
    const int tid  = threadIdx.x;
    const int blk  = blockIdx.x;
    const int w    = tid >> 5;
    const int lane = tid & 31;

    if (tid < NEXP) base_s[tid] = g_blockBase[blk * NEXP + tid];
    for (int i = tid; i < 4 * NEXP; i += 128) (&warpHist[0][0])[i] = 0;
    __syncthreads();

    const int flat = blk * 128 + tid;   // flat (token, slot) index, block-contiguous
    const int e    = g_flat_idx[flat];

    unsigned m      = __match_any_sync(0xffffffffu, e);
    unsigned below  = m & ((1u << lane) - 1u);
    int rank = __popc(below);
    if (below == 0) warpHist[w][e] = __popc(m);     // lowest lane of group
    __syncthreads();

    int prev = 0;
#pragma unroll
    for (int ww = 0; ww < 3; ++ww)
        if (ww < w) prev += warpHist[ww][e];

    const int pos = base_s[e] + prev + rank;
    out[OFF_TOK + pos]  = (float)(flat >> 1);       // token index
    out[OFF_REV + flat] = (float)pos;               // sorted position of flat idx
}

// ---------------------------------------------------------------------------
extern "C" void kernel_launch(void* const* d_in, const int* in_sizes, int n_in,
                              void* d_out, int out_size)
{
    const float* A = (const float*)d_in[0];   // inputs    [16384, 2048] fp32
    const float* W = (const float*)d_in[1];   // wg_weight [64, 2048]    fp32
    float* out = (float*)d_out;

    gate_fused_kernel<<<NBLK, THREADS>>>(A, W, out);
    gate_scan_kernel<<<1, NEXP>>>(out);
    gate_scatter_kernel<<<NBLK, 128>>>(out);
}

// round 2
// speedup vs baseline: 1.2615x; 1.2615x over previous
#include <cuda_runtime.h>
#include <math.h>

// Problem constants
#define NTOK 16384
#define DIM  2048
#define NEXP 64
#define NK   (NTOK * 2)          // 32768 (token, slot) pairs

// GEMM tiling
#define BM 64                    // tokens per CTA
#define BK 32                    // k-chunk
#define BKH (BK / 2)             // packed k pairs
#define THREADS 128
#define NBLK (NTOK / BM)         // 256 CTAs
#define NT  (DIM / BK)           // 64 k-tiles

// Output layout: concatenation of reference return values (all as fp32)
#define OFF_TOK   0
#define OFF_REV   NK
#define OFF_CW    (2 * NK)
#define OFF_SPL   (3 * NK)
#define OFF_PROBS (3 * NK + NEXP)

// Scratch (no allocations allowed -> __device__ globals)
__device__ int g_flat_idx[NK];
__device__ int g_blockHist[NBLK * NEXP];
__device__ int g_blockBase[NBLK * NEXP];

// ---------------------------------------------------------------------------
// Kernel 1: fused GEMM (logits) + softmax + top-2 + combine weights + probs
//           + per-block expert histogram.
// Packed f32x2 FMA over the K dimension (even k -> lo lane, odd k -> hi lane),
// double-buffered smem, register prefetch of the next tile.
// ---------------------------------------------------------------------------
struct GemmBufs {
    float  As[2][BM][36];            // [buf][token][k]  row stride 36 (16B aligned)
    float2 Ws[2][BKH][NEXP + 1];     // [buf][k2][expert] = (W[e][2k2], W[e][2k2+1])
};

union SmemU {
    GemmBufs g;
    float Cs[BM][NEXP + 1];          // probs staging, reused after GEMM
};

__global__ __launch_bounds__(THREADS) void gate_fused_kernel(
    const float* __restrict__ A,   // [NTOK, DIM]
    const float* __restrict__ W,   // [NEXP, DIM]
    float* __restrict__ out)
{
    __shared__ SmemU su;
    __shared__ int   hist[NEXP];

    const int tid  = threadIdx.x;
    const int blk  = blockIdx.x;
    const int tok0 = blk * BM;

    const int tx = tid & 15;         // experts tx, tx+16, tx+32, tx+48
    const int ty = tid >> 4;         // tokens  ty, ty+8, ..., ty+56

    const int lrA = tid >> 3;        // loader row (0..15), +16*p
    const int lcA = tid & 7;         // loader float4 col

    const float* Ablk = A + (size_t)tok0 * DIM;

    float4 pa[4], pw[4];

    // ---- loaders -----------------------------------------------------------
    auto ldTile = [&](int k0) {
#pragma unroll
        for (int p = 0; p < 4; ++p) {
            int r = lrA + 16 * p;
            pa[p] = *reinterpret_cast<const float4*>(Ablk + (size_t)r * DIM + k0 + lcA * 4);
        }
#pragma unroll
        for (int p = 0; p < 4; ++p) {
            int idx = p * 128 + tid;
            int e = idx >> 3, c = idx & 7;
            pw[p] = *reinterpret_cast<const float4*>(W + (size_t)e * DIM + k0 + c * 4);
        }
    };
    auto stTile = [&](int b) {
#pragma unroll
        for (int p = 0; p < 4; ++p) {
            int r = lrA + 16 * p;
            *reinterpret_cast<float4*>(&su.g.As[b][r][lcA * 4]) = pa[p];
        }
#pragma unroll
        for (int p = 0; p < 4; ++p) {
            int idx = p * 128 + tid;
            int e = idx >> 3, c = idx & 7;
            su.g.Ws[b][2 * c][e]     = make_float2(pw[p].x, pw[p].y);
            su.g.Ws[b][2 * c + 1][e] = make_float2(pw[p].z, pw[p].w);
        }
    };

    // ---- mainloop ----------------------------------------------------------
    unsigned long long acc[8][4];
#pragma unroll
    for (int i = 0; i < 8; i++)
#pragma unroll
        for (int j = 0; j < 4; j++) acc[i][j] = 0ull;

    ldTile(0);
    stTile(0);
    __syncthreads();

    int buf = 0;
    for (int t = 0; t < NT; ++t) {
        if (t + 1 < NT) ldTile((t + 1) * BK);

#pragma unroll
        for (int k2 = 0; k2 < BKH; ++k2) {
            unsigned long long a2[8], w2[4];
#pragma unroll
            for (int i = 0; i < 8; i++)
                a2[i] = *reinterpret_cast<const unsigned long long*>(
                            &su.g.As[buf][ty + 8 * i][2 * k2]);
#pragma unroll
            for (int j = 0; j < 4; j++)
                w2[j] = *reinterpret_cast<const unsigned long long*>(
                            &su.g.Ws[buf][k2][tx + 16 * j]);
#pragma unroll
            for (int i = 0; i < 8; i++)
#pragma unroll
                for (int j = 0; j < 4; j++)
                    asm("fma.rn.f32x2 %0, %1, %2, %0;"
                        : "+l"(acc[i][j]) : "l"(a2[i]), "l"(w2[j]));
        }

        if (t + 1 < NT) stTile(buf ^ 1);
        __syncthreads();
        buf ^= 1;
    }

    // ---- epilogue: logits -> Cs (union reuse is safe: sync above) ----------
#pragma unroll
    for (int i = 0; i < 8; i++)
#pragma unroll
        for (int j = 0; j < 4; j++) {
            unsigned long long v = acc[i][j];
            float lo = __uint_as_float((unsigned)v);
            float hi = __uint_as_float((unsigned)(v >> 32));
            su.Cs[ty + 8 * i][tx + 16 * j] = lo + hi;
        }
    if (tid < NEXP) hist[tid] = 0;
    __syncthreads();

    // One thread per token: softmax + top-2 + combine weights
    if (tid < BM) {
        const int t = tid;
        float mx = -1e30f;
#pragma unroll 8
        for (int e = 0; e < NEXP; e++) mx = fmaxf(mx, su.Cs[t][e]);
        float s = 0.f;
#pragma unroll 8
        for (int e = 0; e < NEXP; e++) {
            float ex = expf(su.Cs[t][e] - mx);
            su.Cs[t][e] = ex;
            s += ex;
        }
        float inv = 1.0f / s;
        float v1 = -1.f, v2 = -1.f;
        int   i1 = 0, i2 = 0;
#pragma unroll 8
        for (int e = 0; e < NEXP; e++) {
            float p = su.Cs[t][e] * inv;
            su.Cs[t][e] = p;                    // probs in place
            if (p > v1)      { v2 = v1; i2 = i1; v1 = p; i1 = e; }
            else if (p > v2) { v2 = p; i2 = e; }
        }
        // combine = softmax([v1, v2]) over the prob VALUES (reference quirk)
        float eb   = expf(v2 - v1);             // v1 >= v2
        float invd = 1.0f / (1.0f + eb);
        int flat = (tok0 + t) * 2;
        out[OFF_CW + flat]     = invd;
        out[OFF_CW + flat + 1] = eb * invd;
        g_flat_idx[flat]     = i1;
        g_flat_idx[flat + 1] = i2;
        atomicAdd(&hist[i1], 1);
        atomicAdd(&hist[i2], 1);
    }
    __syncthreads();

    if (tid < NEXP) g_blockHist[blk * NEXP + tid] = hist[tid];

    // Coalesced probs writeback
    float* pout = out + OFF_PROBS + (size_t)tok0 * NEXP;
    for (int idx = tid; idx < BM * NEXP; idx += THREADS) {
        int t = idx >> 6, e = idx & 63;
        pout[idx] = su.Cs[t][e];
    }
}

// ---------------------------------------------------------------------------
// Kernel 2 (1 CTA, 1024 threads): per-expert scan across blocks + expert
// offsets. 16 chunks of 16 blocks per expert for parallelism.
// ---------------------------------------------------------------------------
__global__ __launch_bounds__(1024) void gate_scan_kernel(float* __restrict__ out)
{
    __shared__ int part[16][NEXP];
    __shared__ int totals[NEXP];
    __shared__ int offs[NEXP];
    const int tid = threadIdx.x;
    const int e = tid & 63;
    const int c = tid >> 6;          // chunk 0..15

    int s = 0;
#pragma unroll
    for (int b = c * 16; b < c * 16 + 16; b++) s += g_blockHist[b * NEXP + e];
    part[c][e] = s;
    __syncthreads();

    if (tid < NEXP) {
        int run = 0;
#pragma unroll
        for (int cc = 0; cc < 16; cc++) run += part[cc][e];
        totals[e] = run;
        out[OFF_SPL + e] = (float)run;
    }
    __syncthreads();

    if (tid == 0) {
        int a = 0;
        for (int i = 0; i < NEXP; i++) { offs[i] = a; a += totals[i]; }
    }
    __syncthreads();

    int base = offs[e];
    for (int cc = 0; cc < c; cc++) base += part[cc][e];
#pragma unroll
    for (int b = c * 16; b < c * 16 + 16; b++) {
        g_blockBase[b * NEXP + e] = base;
        base += g_blockHist[b * NEXP + e];
    }
}

// ---------------------------------------------------------------------------
// Kernel 3 (NBLK x 128): stable intra-block rank (match_any + warp histogram
// prefix) -> final sorted position; scatter token_order / reversed_ordering.
// ---------------------------------------------------------------------------
__global__ __launch_bounds__(128) void gate_scatter_kernel(float* __restrict__ out)
{
    __shared__ int warpHist[4][NEXP];
    __shared__ int base_s[NEXP];
    const int tid  = threadIdx.x;
    const int blk  = blockIdx.x;
    const int w    = tid >> 5;
    const int lane = tid & 31;

    if (tid < NEXP) base_s[tid] = g_blockBase[blk * NEXP + tid];
    for (int i = tid; i < 4 * NEXP; i += 128) (&warpHist[0][0])[i] = 0;
    __syncthreads();

    const int flat = blk * 128 + tid;   // flat (token, slot) index, block-contiguous
    const int e    = g_flat_idx[flat];

    unsigned m      = __match_any_sync(0xffffffffu, e);
    unsigned below  = m & ((1u << lane) - 1u);
    int rank = __popc(below);
    if (below == 0) warpHist[w][e] = __popc(m);     // lowest lane of group
    __syncthreads();

    int prev = 0;
#pragma unroll
    for (int ww = 0; ww < 3; ++ww)
        if (ww < w) prev += warpHist[ww][e];

    const int pos = base_s[e] + prev + rank;
    out[OFF_TOK + pos]  = (float)(flat >> 1);       // token index
    out[OFF_REV + flat] = (float)pos;               // sorted position of flat idx
}

// ---------------------------------------------------------------------------
extern "C" void kernel_launch(void* const* d_in, const int* in_sizes, int n_in,
                              void* d_out, int out_size)
{
    const float* A = (const float*)d_in[0];   // inputs    [16384, 2048] fp32
    const float* W = (const float*)d_in[1];   // wg_weight [64, 2048]    fp32
    float* out = (float*)d_out;

    gate_fused_kernel<<<NBLK, THREADS>>>(A, W, out);
    gate_scan_kernel<<<1, 1024>>>(out);
    gate_scatter_kernel<<<NBLK, 128>>>(out);
}